// round 12
// baseline (speedup 1.0000x reference)
#include <cuda_runtime.h>

// LatticeQuantizer: hierarchical nested E8 lattice quantize (M=3, Q=4).
// R12 = R10 proven-bit-exact numerics + 2 independent rows per thread
// (fills issue-slot gaps; kernel is scheduler-issue-bound) + one exact
// micro-cut in yB construction. No f32x2 (R11 proved it spills to local).

#define TINY_F 1.1920928955078125e-07f  // np.finfo(float32).eps

static __device__ __forceinline__ float cround(float x) {
    float s = copysignf(TINY_F, x);
    return floorf((x - s) + 0.5f);
}

// ---- encode-path closest point (R10-verbatim decisions) ----
static __device__ __forceinline__ void cp_e8_enc(const float x[8], float out[8]) {
    float rA[8]; float sA = 0.f;
#pragma unroll
    for (int i = 0; i < 8; i++) {
        float f = cround(x[i]);
        rA[i] = x[i] - f;          // exact
        sA += f;                   // exact (small ints)
    }
    float rkA = rA[0]; int kA = 0;
#pragma unroll
    for (int i = 1; i < 8; i++) {
        bool gt = fabsf(rA[i]) > fabsf(rkA);   // FIRST max wins
        rkA = gt ? rA[i] : rkA;
        kA  = gt ? i     : kA;
    }
    float tieA  = (x[0] >= 0.f) ? -1.f : 1.f;
    float stepA = (rkA > 0.f) ? 1.f : ((rkA < 0.f) ? -1.f : tieA);
    bool oddA = (((int)sA) & 1) != 0;
    int  kAe  = oddA ? kA : 8;
    float rcA = rkA - stepA;

    float rB[8], fB[8]; float sB = 0.f;
#pragma unroll
    for (int i = 0; i < 8; i++) {
        float xs = x[i] - 0.5f;    // reference computes the same fl
        float f  = cround(xs);
        fB[i] = f;
        rB[i] = xs - f;
        sB += f;
    }
    float rkB = rB[0]; int kB = 0;
#pragma unroll
    for (int i = 1; i < 8; i++) {
        bool gt = fabsf(rB[i]) > fabsf(rkB);
        rkB = gt ? rB[i] : rkB;
        kB  = gt ? i     : kB;
    }
    float tieB  = ((x[0] - 0.5f) >= 0.f) ? -1.f : 1.f;
    float stepB = (rkB > 0.f) ? 1.f : ((rkB < 0.f) ? -1.f : tieB);
    bool oddB = (((int)sB) & 1) != 0;
    int  kBe  = oddB ? kB : 8;

    // yB = (fB + addB) + 0.5 == fB + (addB + 0.5): both exact half-int adds
    float stepB_h = stepB + 0.5f;   // exact
    float d0 = 0.f, d1 = 0.f;
    float yB[8];
#pragma unroll
    for (int i = 0; i < 8; i++) {
        float addBh = (i == kBe) ? stepB_h : 0.5f;
        yB[i] = fB[i] + addBh;                 // exact, == reference value
        float a  = (i == kAe) ? rcA : rA[i];
        float rb = x[i] - yB[i];
        d0 = __fadd_rn(d0, __fmul_rn(a, a));
        d1 = __fadd_rn(d1, __fmul_rn(rb, rb));
    }
    bool p0 = d0 < d1;
#pragma unroll
    for (int i = 0; i < 8; i++) {
        float addA = (i == kAe) ? stepA : 0.f;
        float oA = (x[i] - rA[i]) + addA;      // fA exact, +-1 exact
        out[i] = p0 ? oA : yB[i];
    }
}

// ---- decode-path residuals: v = gq - cp_e8(gq) (exact eighths domain) ----
static __device__ __forceinline__ void cp_e8_dec_res(const float x[8], float v[8]) {
    float rA[8]; float sA = 0.f;
#pragma unroll
    for (int i = 0; i < 8; i++) {
        float f = cround(x[i]);
        rA[i] = x[i] - f;
        sA += f;
    }
    float rkA = rA[0]; int kA = 0;
#pragma unroll
    for (int i = 1; i < 8; i++) {
        bool gt = fabsf(rA[i]) > fabsf(rkA);
        rkA = gt ? rA[i] : rkA;
        kA  = gt ? i     : kA;
    }
    float tieA  = (x[0] >= 0.f) ? -1.f : 1.f;
    float stepA = (rkA > 0.f) ? 1.f : ((rkA < 0.f) ? -1.f : tieA);
    bool oddA = (((int)sA) & 1) != 0;
    int  kAe  = oddA ? kA : 8;
    float rcA = rkA - stepA;

    float rB[8]; float sB = 0.f;
#pragma unroll
    for (int i = 0; i < 8; i++) {
        float xs = x[i] - 0.5f;    // exact here (x on 1/8 grid)
        float f  = cround(xs);
        rB[i] = xs - f;
        sB += f;
    }
    float rkB = rB[0]; int kB = 0;
#pragma unroll
    for (int i = 1; i < 8; i++) {
        bool gt = fabsf(rB[i]) > fabsf(rkB);
        rkB = gt ? rB[i] : rkB;
        kB  = gt ? i     : kB;
    }
    float tieB  = ((x[0] - 0.5f) >= 0.f) ? -1.f : 1.f;
    float stepB = (rkB > 0.f) ? 1.f : ((rkB < 0.f) ? -1.f : tieB);
    bool oddB = (((int)sB) & 1) != 0;
    int  kBe  = oddB ? kB : 8;
    float rcB = rkB - stepB;

    // exact-domain distances: FMA sums + tie adjustment (bisect-proven)
    float d0 = 0.f, d1 = 0.f;
#pragma unroll
    for (int i = 0; i < 8; i++) {
        d0 = __fmaf_rn(rA[i], rA[i], d0);
        d1 = __fmaf_rn(rB[i], rB[i], d1);
    }
    float adjA = __fmul_rn(rcA, rcA) - __fmul_rn(rkA, rkA);  // exact
    float adjB = __fmul_rn(rcB, rcB) - __fmul_rn(rkB, rkB);
    d0 += oddA ? adjA : 0.f;
    d1 += oddB ? adjB : 0.f;
    bool p0 = d0 < d1;

    int   ksel = p0 ? kAe : kBe;
    float rcs  = p0 ? rcA : rcB;
#pragma unroll
    for (int i = 0; i < 8; i++) {
        float rs = p0 ? rA[i] : rB[i];
        v[i] = (i == ksel) ? rcs : rs;
    }
}

// full per-row pipeline (R10-verbatim numerics)
static __device__ __forceinline__ void process_row(
    const float x[8], const float eps[8], bool beta1, float beta, float xh[8])
{
    float t[8];
#pragma unroll
    for (int i = 0; i < 8; i++) {
        float xl = beta1 ? x[i] : __fdiv_rn(x[i], beta);
        t[i] = xl + eps[i];
    }
#pragma unroll
    for (int i = 0; i < 8; i++) xh[i] = 0.f;

#pragma unroll
    for (int m = 0; m < 3; m++) {
        float cp[8];
        cp_e8_enc(t, cp);

        // z = cp @ G_inv (analytic forward solve; exact quarter-integers)
        float z[8];
        z[0] = 0.5f * cp[0];
        float sum06 = z[0];
#pragma unroll
        for (int i = 1; i < 7; i++) { z[i] = cp[i] + z[i - 1]; sum06 += z[i]; }
        z[7] = 2.f * cp[7] - sum06;

        // b = custom_round(fmod(z,4)); fmod exact; cround REQUIRED
        float b[8];
#pragma unroll
        for (int i = 0; i < 8; i++) {
            float q = truncf(z[i] * 0.25f);
            float r = __fmaf_rn(-4.f, q, z[i]);   // exact (dyadic)
            b[i] = cround(r);
        }

        // next layer: t = fma(cp, 1/Q, eps) == fl(fl(cp*0.25)+eps)
        if (m < 2) {
#pragma unroll
            for (int i = 0; i < 8; i++)
                t[i] = __fmaf_rn(cp[i], 0.25f, eps[i]);
        }

        // decode layer m: xi = g - 4*cp_e8(g/4) == 4*v
        float h = 0.5f * b[7];
        float g[8];
        g[0] = 2.f * b[0] - b[1] + h;
#pragma unroll
        for (int j = 1; j < 6; j++) g[j] = b[j] - b[j + 1] + h;
        g[6] = b[6] + h;
        g[7] = h;

        float gq[8];
#pragma unroll
        for (int i = 0; i < 8; i++) gq[i] = g[i] * 0.25f;   // exact eighths
        float v[8];
        cp_e8_dec_res(gq, v);

        float c4 = (m == 0) ? 4.f : ((m == 1) ? 16.f : 64.f);
#pragma unroll
        for (int i = 0; i < 8; i++)
            xh[i] = __fmaf_rn(c4, v[i], xh[i]);            // exact dyadic
    }
}

__global__ void __launch_bounds__(256)
lq_kernel(const float4* __restrict__ xin,
          const float* __restrict__ betap,
          const float* __restrict__ epsp,
          float4* __restrict__ outp,
          int nrows)
{
    int tid  = blockIdx.x * blockDim.x + threadIdx.x;
    int row0 = 2 * tid;
    if (row0 >= nrows) return;
    bool has1 = (row0 + 1) < nrows;

    float beta = __ldg(betap);
    bool beta1 = (beta == 1.0f);
    float eps[8];
#pragma unroll
    for (int i = 0; i < 8; i++) eps[i] = __ldg(epsp + i);

    // two independent rows -> two independent dependency chains for ILP
    float4 a0 = __ldg(xin + 2 * row0);
    float4 a1 = __ldg(xin + 2 * row0 + 1);
    float4 b0, b1;
    if (has1) {
        b0 = __ldg(xin + 2 * row0 + 2);
        b1 = __ldg(xin + 2 * row0 + 3);
    } else {
        b0 = a0; b1 = a1;
    }

    float xA[8] = {a0.x, a0.y, a0.z, a0.w, a1.x, a1.y, a1.z, a1.w};
    float xB[8] = {b0.x, b0.y, b0.z, b0.w, b1.x, b1.y, b1.z, b1.w};

    float hA[8], hB[8];
    process_row(xA, eps, beta1, beta, hA);
    process_row(xB, eps, beta1, beta, hB);

    float4 oA0, oA1, oB0, oB1;
    if (beta1) {
        oA0 = make_float4(hA[0], hA[1], hA[2], hA[3]);
        oA1 = make_float4(hA[4], hA[5], hA[6], hA[7]);
        oB0 = make_float4(hB[0], hB[1], hB[2], hB[3]);
        oB1 = make_float4(hB[4], hB[5], hB[6], hB[7]);
    } else {
        oA0 = make_float4(beta*hA[0], beta*hA[1], beta*hA[2], beta*hA[3]);
        oA1 = make_float4(beta*hA[4], beta*hA[5], beta*hA[6], beta*hA[7]);
        oB0 = make_float4(beta*hB[0], beta*hB[1], beta*hB[2], beta*hB[3]);
        oB1 = make_float4(beta*hB[4], beta*hB[5], beta*hB[6], beta*hB[7]);
    }
    outp[2 * row0]     = oA0;
    outp[2 * row0 + 1] = oA1;
    if (has1) {
        outp[2 * row0 + 2] = oB0;
        outp[2 * row0 + 3] = oB1;
    }
}

extern "C" void kernel_launch(void* const* d_in, const int* in_sizes, int n_in,
                              void* d_out, int out_size)
{
    const float* x = (const float*)d_in[0];
    const float* beta = nullptr;
    const float* eps  = nullptr;
    for (int i = 1; i < n_in; i++) {
        if (in_sizes[i] == 1) beta = (const float*)d_in[i];
        else if (in_sizes[i] == 8) eps = (const float*)d_in[i];
    }
    int nrows = in_sizes[0] / 8;
    int nthreads_total = (nrows + 1) / 2;     // 2 rows per thread
    int threads = 256;
    int blocks = (nthreads_total + threads - 1) / threads;
    lq_kernel<<<blocks, threads>>>((const float4*)x, beta, eps, (float4*)d_out, nrows);
}

// round 13
// speedup vs baseline: 1.1618x; 1.1618x over previous
#include <cuda_runtime.h>

// LatticeQuantizer: hierarchical nested E8 lattice quantize (M=3, Q=4).
// R13 = R10 (best, 231.8us) + three proven-safe cuts:
//  - yB = fB + (addB+0.5)  [bit-exact, verified in R12 pass]
//  - encode output from kept fA (reference: f + 0*step == f bitwise)
//  - tree argmax (left-priority max is associative; same first-max result,
//    depth 3 instead of 7 -> shorter encode critical path)
// One row per thread (R11/R12 proved more per-thread state regresses).

#define TINY_F 1.1920928955078125e-07f  // np.finfo(float32).eps

static __device__ __forceinline__ float cround(float x) {
    float s = copysignf(TINY_F, x);
    return floorf((x - s) + 0.5f);
}

// left-priority (FIRST max) argmax over 8 lanes, tree form.
// merge(a,b): take b only if |b.v| > |a.v| (a = earlier index side).
static __device__ __forceinline__ void argmax8(const float r[8], float& rk, int& k)
{
    float v01 = (fabsf(r[1]) > fabsf(r[0])) ? r[1] : r[0];
    int   k01 = (fabsf(r[1]) > fabsf(r[0])) ? 1    : 0;
    float v23 = (fabsf(r[3]) > fabsf(r[2])) ? r[3] : r[2];
    int   k23 = (fabsf(r[3]) > fabsf(r[2])) ? 3    : 2;
    float v45 = (fabsf(r[5]) > fabsf(r[4])) ? r[5] : r[4];
    int   k45 = (fabsf(r[5]) > fabsf(r[4])) ? 5    : 4;
    float v67 = (fabsf(r[7]) > fabsf(r[6])) ? r[7] : r[6];
    int   k67 = (fabsf(r[7]) > fabsf(r[6])) ? 7    : 6;

    bool g0 = fabsf(v23) > fabsf(v01);
    float va = g0 ? v23 : v01;  int ka = g0 ? k23 : k01;
    bool g1 = fabsf(v67) > fabsf(v45);
    float vb = g1 ? v67 : v45;  int kb = g1 ? k67 : k45;

    bool gf = fabsf(vb) > fabsf(va);
    rk = gf ? vb : va;
    k  = gf ? kb : ka;
}

// ---- encode-path closest point (decision numerics R10-verbatim) ----
static __device__ __forceinline__ void cp_e8_enc(const float x[8], float out[8]) {
    float fA[8], rA[8]; float sA = 0.f;
#pragma unroll
    for (int i = 0; i < 8; i++) {
        fA[i] = cround(x[i]);
        rA[i] = x[i] - fA[i];      // exact
        sA += fA[i];               // exact (small ints)
    }
    float rkA; int kA;
    argmax8(rA, rkA, kA);
    float tieA  = (x[0] >= 0.f) ? -1.f : 1.f;  // rk==0 => all r==0 => k==0
    float stepA = (rkA > 0.f) ? 1.f : ((rkA < 0.f) ? -1.f : tieA);
    bool oddA = (((int)sA) & 1) != 0;
    int  kAe  = oddA ? kA : 8;
    float rcA = rkA - stepA;       // fl == fl(x_k - (fA_k + step))

    float fB[8], rB[8]; float sB = 0.f;
#pragma unroll
    for (int i = 0; i < 8; i++) {
        float xs = x[i] - 0.5f;    // reference computes the same fl
        fB[i] = cround(xs);
        rB[i] = xs - fB[i];        // exact relative to xs
        sB += fB[i];
    }
    float rkB; int kB;
    argmax8(rB, rkB, kB);
    float tieB  = ((x[0] - 0.5f) >= 0.f) ? -1.f : 1.f;
    float stepB = (rkB > 0.f) ? 1.f : ((rkB < 0.f) ? -1.f : tieB);
    bool oddB = (((int)sB) & 1) != 0;
    int  kBe  = oddB ? kB : 8;

    // yB = (fB + addB) + 0.5 == fB + (addB + 0.5): exact half-int adds
    float stepB_h = stepB + 0.5f;  // exact
    float d0 = 0.f, d1 = 0.f;
    float yB[8];
#pragma unroll
    for (int i = 0; i < 8; i++) {
        float addBh = (i == kBe) ? stepB_h : 0.5f;
        yB[i] = fB[i] + addBh;                 // exact, == reference value
        float a  = (i == kAe) ? rcA : rA[i];
        float rb = x[i] - yB[i];
        d0 = __fadd_rn(d0, __fmul_rn(a, a));   // reference sequential order
        d1 = __fadd_rn(d1, __fmul_rn(rb, rb));
    }
    bool p0 = d0 < d1;
#pragma unroll
    for (int i = 0; i < 8; i++) {
        float oA = fA[i];                      // reference: f + 0*step == f
        if (i == kAe) oA += stepA;             // exact +-1 at flip lane
        out[i] = p0 ? oA : yB[i];
    }
}

// ---- decode-path residuals: v = gq - cp_e8(gq) (exact eighths domain) ----
static __device__ __forceinline__ void cp_e8_dec_res(const float x[8], float v[8]) {
    float rA[8]; float sA = 0.f;
#pragma unroll
    for (int i = 0; i < 8; i++) {
        float f = cround(x[i]);
        rA[i] = x[i] - f;
        sA += f;
    }
    float rkA; int kA;
    argmax8(rA, rkA, kA);
    float tieA  = (x[0] >= 0.f) ? -1.f : 1.f;
    float stepA = (rkA > 0.f) ? 1.f : ((rkA < 0.f) ? -1.f : tieA);
    bool oddA = (((int)sA) & 1) != 0;
    int  kAe  = oddA ? kA : 8;
    float rcA = rkA - stepA;

    float rB[8]; float sB = 0.f;
#pragma unroll
    for (int i = 0; i < 8; i++) {
        float xs = x[i] - 0.5f;    // exact here (x on 1/8 grid)
        float f  = cround(xs);
        rB[i] = xs - f;
        sB += f;
    }
    float rkB; int kB;
    argmax8(rB, rkB, kB);
    float tieB  = ((x[0] - 0.5f) >= 0.f) ? -1.f : 1.f;
    float stepB = (rkB > 0.f) ? 1.f : ((rkB < 0.f) ? -1.f : tieB);
    bool oddB = (((int)sB) & 1) != 0;
    int  kBe  = oddB ? kB : 8;
    float rcB = rkB - stepB;

    // exact-domain distances: FMA sums + tie adjustment (bisect-proven)
    float d0 = 0.f, d1 = 0.f;
#pragma unroll
    for (int i = 0; i < 8; i++) {
        d0 = __fmaf_rn(rA[i], rA[i], d0);
        d1 = __fmaf_rn(rB[i], rB[i], d1);
    }
    float adjA = __fmul_rn(rcA, rcA) - __fmul_rn(rkA, rkA);  // exact
    float adjB = __fmul_rn(rcB, rcB) - __fmul_rn(rkB, rkB);
    d0 += oddA ? adjA : 0.f;
    d1 += oddB ? adjB : 0.f;
    bool p0 = d0 < d1;

    int   ksel = p0 ? kAe : kBe;
    float rcs  = p0 ? rcA : rcB;
#pragma unroll
    for (int i = 0; i < 8; i++) {
        float rs = p0 ? rA[i] : rB[i];
        v[i] = (i == ksel) ? rcs : rs;
    }
}

__global__ void __launch_bounds__(256)
lq_kernel(const float4* __restrict__ xin,
          const float* __restrict__ betap,
          const float* __restrict__ epsp,
          float4* __restrict__ outp,
          int nrows)
{
    int row = blockIdx.x * blockDim.x + threadIdx.x;
    if (row >= nrows) return;

    float beta = __ldg(betap);
    float eps[8];
#pragma unroll
    for (int i = 0; i < 8; i++) eps[i] = __ldg(epsp + i);

    float4 a0 = __ldg(xin + 2 * row);
    float4 a1 = __ldg(xin + 2 * row + 1);
    float x[8] = {a0.x, a0.y, a0.z, a0.w, a1.x, a1.y, a1.z, a1.w};

    bool beta1 = (beta == 1.0f);

    // layer-0 encode input: t = x/beta + eps (x/1.0 == x bitwise)
    float t[8];
#pragma unroll
    for (int i = 0; i < 8; i++) {
        float xl = beta1 ? x[i] : __fdiv_rn(x[i], beta);
        t[i] = xl + eps[i];
    }

    float xh[8] = {0.f, 0.f, 0.f, 0.f, 0.f, 0.f, 0.f, 0.f};

#pragma unroll
    for (int m = 0; m < 3; m++) {
        // ---- encode layer m ----
        float cp[8];
        cp_e8_enc(t, cp);

        // z = cp @ G_inv (analytic forward solve; exact quarter-integers)
        float z[8];
        z[0] = 0.5f * cp[0];
        float sum06 = z[0];
#pragma unroll
        for (int i = 1; i < 7; i++) { z[i] = cp[i] + z[i - 1]; sum06 += z[i]; }
        z[7] = 2.f * cp[7] - sum06;

        // b = custom_round(fmod(z,4)); fmod exact; cround REQUIRED
        float b[8];
#pragma unroll
        for (int i = 0; i < 8; i++) {
            float q = truncf(z[i] * 0.25f);
            float r = __fmaf_rn(-4.f, q, z[i]);   // exact (dyadic)
            b[i] = cround(r);
        }

        // next layer input: t = fma(cp, 1/Q, eps) == fl(fl(cp*0.25)+eps)
        if (m < 2) {
#pragma unroll
            for (int i = 0; i < 8; i++)
                t[i] = __fmaf_rn(cp[i], 0.25f, eps[i]);
        }

        // ---- decode layer m: xi = g - 4*cp_e8(g/4) == 4*v ----
        float h = 0.5f * b[7];
        float g[8];
        g[0] = 2.f * b[0] - b[1] + h;
#pragma unroll
        for (int j = 1; j < 6; j++) g[j] = b[j] - b[j + 1] + h;
        g[6] = b[6] + h;
        g[7] = h;

        float gq[8];
#pragma unroll
        for (int i = 0; i < 8; i++) gq[i] = g[i] * 0.25f;   // exact eighths
        float v[8];
        cp_e8_dec_res(gq, v);

        // xh += scale * xi = (4*scale) * v  — all exact dyadic
        float c4 = (m == 0) ? 4.f : ((m == 1) ? 16.f : 64.f);
#pragma unroll
        for (int i = 0; i < 8; i++)
            xh[i] = __fmaf_rn(c4, v[i], xh[i]);
    }

    float4 o0, o1;
    if (beta1) {
        o0.x = xh[0]; o0.y = xh[1]; o0.z = xh[2]; o0.w = xh[3];
        o1.x = xh[4]; o1.y = xh[5]; o1.z = xh[6]; o1.w = xh[7];
    } else {
        o0.x = beta * xh[0]; o0.y = beta * xh[1];
        o0.z = beta * xh[2]; o0.w = beta * xh[3];
        o1.x = beta * xh[4]; o1.y = beta * xh[5];
        o1.z = beta * xh[6]; o1.w = beta * xh[7];
    }
    outp[2 * row]     = o0;
    outp[2 * row + 1] = o1;
}

extern "C" void kernel_launch(void* const* d_in, const int* in_sizes, int n_in,
                              void* d_out, int out_size)
{
    const float* x = (const float*)d_in[0];
    const float* beta = nullptr;
    const float* eps  = nullptr;
    for (int i = 1; i < n_in; i++) {
        if (in_sizes[i] == 1) beta = (const float*)d_in[i];
        else if (in_sizes[i] == 8) eps = (const float*)d_in[i];
    }
    int nrows = in_sizes[0] / 8;
    int threads = 256;
    int blocks = (nrows + threads - 1) / threads;
    lq_kernel<<<blocks, threads>>>((const float4*)x, beta, eps, (float4*)d_out, nrows);
}